// round 11
// baseline (speedup 1.0000x reference)
#include <cuda_runtime.h>
#include <cuda_bf16.h>
#include <cstdint>

// ---------------- problem constants ----------------
#define Bc 16
#define Dc 64
#define Tc 8192
#define Kc 512
#define DT (Dc * Tc)        // 524288
#define BT (Bc * Tc)        // 131072
#define THREADS 256
#define GRID 148
#define NTILES (BT / 128)   // 1024 token tiles
#define NKT 12              // K=192 in 12 k-tiles of 16
#define CHUNK_BYTES (128 * 192 * 2)   // one 128-codeword chunk, bf16, 49152 B
#define WIN 1e-4f           // >> 2*(mma err ~1e-6 + ref grain ~1.2e-5)

// ---------------- smem layout ----------------
#define SM_CN 0                            // 512 f32
#define SM_A  2048                         // 128x192 bf16, tiled 16x16
#define SM_B0 (SM_A + CHUNK_BYTES)         // 51200
#define SM_B1 (SM_B0 + CHUNK_BYTES)        // 100352
#define SM_SC (SM_B1 + CHUNK_BYTES)        // 149504: scores [128][SSTR] f32
#define SSTR 130
#define SMEM_TOTAL (SM_SC + 128 * SSTR * 4)  // 216064 B

// scratch (no cudaMalloc allowed): prebaked bf16 B tiles + codeword norms
__device__ __align__(16) unsigned char g_B[4 * CHUNK_BYTES];
__device__ float g_cn[Kc];

// ---------------- helpers ----------------
__device__ __forceinline__ uint32_t smem_u32(const void* p) {
    uint32_t a;
    asm("{ .reg .u64 t; cvta.to.shared.u64 t, %1; cvt.u32.u64 %0, t; }"
        : "=r"(a) : "l"(p));
    return a;
}

#define LDSM4(r0, r1, r2, r3, addr)                                          \
    asm volatile("ldmatrix.sync.aligned.m8n8.x4.shared.b16 {%0,%1,%2,%3}, [%4];" \
        : "=r"(r0), "=r"(r1), "=r"(r2), "=r"(r3) : "r"(addr))

#define MMA_BF16(c, a0, a1, a2, a3, b0, b1)                                  \
    asm volatile("mma.sync.aligned.m16n8k16.row.col.f32.bf16.bf16.f32 "      \
        "{%0,%1,%2,%3}, {%4,%5,%6,%7}, {%8,%9}, {%0,%1,%2,%3};"              \
        : "+f"((c)[0]), "+f"((c)[1]), "+f"((c)[2]), "+f"((c)[3])             \
        : "r"(a0), "r"(a1), "r"(a2), "r"(a3), "r"(b0), "r"(b1))

#define TOP4(s, k) do {                                                      \
    float _s = (s); int _k = (k);                                            \
    if (_s < b3s) {                                                          \
        if (_s < b0s)      { b3s=b2s;b3k=b2k; b2s=b1s;b2k=b1k; b1s=b0s;b1k=b0k; b0s=_s;b0k=_k; } \
        else if (_s < b1s) { b3s=b2s;b3k=b2k; b2s=b1s;b2k=b1k; b1s=_s;b1k=_k; } \
        else if (_s < b2s) { b3s=b2s;b3k=b2k; b2s=_s;b2k=_k; }               \
        else               { b3s=_s;b3k=_k; }                                \
    } } while (0)

__device__ __forceinline__ uint32_t pack_bf16(__nv_bfloat16 a, __nv_bfloat16 b) {
    uint16_t ua = *(uint16_t*)&a, ub = *(uint16_t*)&b;
    return (uint32_t)ua | ((uint32_t)ub << 16);
}

// copy one 48KB B chunk gmem -> smem via cp.async (12 x 16B per thread)
__device__ __forceinline__ void chunk_async(uint32_t sdst, const unsigned char* gsrc,
                                            int tid) {
    #pragma unroll
    for (int i = 0; i < 12; i++) {
        uint32_t s = sdst + (uint32_t)(tid + i * THREADS) * 16;
        const unsigned char* g = gsrc + (size_t)(tid + i * THREADS) * 16;
        asm volatile("cp.async.cg.shared.global [%0], [%1], 16;" :: "r"(s), "l"(g));
    }
    asm volatile("cp.async.commit_group;" ::: "memory");
}

// ---------------- prep: bake B tiles (bf16 split [ch,cl,ch]) + cn ----------------
// chunk c: tile (kt 0..11, n8 0..15) at (kt*16+n8)*256; in-tile: nrow*32 + kcol*2
__global__ void vq_prep(const float* __restrict__ cb)
{
    int r = blockIdx.x * blockDim.x + threadIdx.x;
    if (r >= Kc) return;
    const float* row = cb + r * Dc;
    unsigned char* base = g_B + (size_t)(r >> 7) * CHUNK_BYTES;
    const int n8 = (r & 127) >> 3, nr = r & 7;
    float cn = 0.f;
    for (int d = 0; d < Dc; d++) {
        float v = row[d];
        cn = __fadd_rn(cn, __fmul_rn(v, v));     // serial ascending (matches ref)
        __nv_bfloat16 ch = __float2bfloat16_rn(v);
        __nv_bfloat16 cl = __float2bfloat16_rn(v - __bfloat162float(ch));
        const int ks[3] = { d, 64 + d, 128 + d };
        const __nv_bfloat16 vs[3] = { ch, cl, ch };
        #pragma unroll
        for (int j = 0; j < 3; j++) {
            int k = ks[j];
            uint32_t off = (uint32_t)(((k >> 4) * 16 + n8) * 256 + nr * 32 + (k & 15) * 2);
            *(__nv_bfloat16*)(base + off) = vs[j];
        }
    }
    g_cn[r] = cn;
}

// ---------------- main ----------------
__global__ __launch_bounds__(THREADS, 1)
void vq_main(const float* __restrict__ x,
             const float* __restrict__ cb,
             float* __restrict__ out,
             int write_second)
{
    extern __shared__ char smem[];
    const uint32_t sb = smem_u32(smem);
    const int tid = threadIdx.x, wid = tid >> 5, lane = tid & 31;
    float* scn = (float*)(smem + SM_CN);
    float* ssc = (float*)(smem + SM_SC);

    for (int i = tid; i < Kc; i += THREADS) scn[i] = g_cn[i];

    // ldmatrix per-lane offsets
    const uint32_t aOff = (uint32_t)(lane & 15) * 32 + (uint32_t)(lane >> 4) * 16;
    const uint32_t bOff = (uint32_t)(lane & 7) * 32 + (uint32_t)((lane >> 3) & 1) * 16
                        + (uint32_t)(lane >> 4) * 256;
    const uint32_t sA = sb + SM_A;
    const uint32_t sBbuf[2] = { sb + SM_B0, sb + SM_B1 };

    for (int tile = blockIdx.x; tile < NTILES; tile += GRID) {
        const int b = tile >> 6, t0 = (tile & 63) * 128;
        const float* xbase = x + (size_t)b * DT + t0;

        // prefetch chunk 0, then build A (overlaps the copy)
        chunk_async(sBbuf[0], g_B, tid);

        // A: [xh, xh, xl] (k 0-63 -> xh, 64-127 -> xh, 128-191 -> xl)
        // tiles 16x16: off = ((tl>>4)*12 + (k>>4))*512 + (tl&15)*32 + (k&15)*2
        for (int i = tid; i < 128 * 32; i += THREADS) {
            const int tl = i & 127, dp = i >> 7;       // d pair (2dp, 2dp+1)
            const float v0 = xbase[(size_t)(2 * dp) * Tc + tl];
            const float v1 = xbase[(size_t)(2 * dp + 1) * Tc + tl];
            const __nv_bfloat16 h0 = __float2bfloat16_rn(v0);
            const __nv_bfloat16 h1 = __float2bfloat16_rn(v1);
            const __nv_bfloat16 l0 = __float2bfloat16_rn(v0 - __bfloat162float(h0));
            const __nv_bfloat16 l1 = __float2bfloat16_rn(v1 - __bfloat162float(h1));
            const uint32_t hp = pack_bf16(h0, h1), lp = pack_bf16(l0, l1);
            const uint32_t rowb = (uint32_t)(tl >> 4) * 12 * 512 + (uint32_t)(tl & 15) * 32;
            const int k0 = 2 * dp;
            #pragma unroll
            for (int j = 0; j < 3; j++) {
                const int k = k0 + j * 64;
                const uint32_t val = (j == 2) ? lp : hp;   // FIX: xl goes in k128-191
                *(uint32_t*)(smem + SM_A + rowb + (uint32_t)(k >> 4) * 512
                             + (uint32_t)(k & 15) * 2) = val;
            }
        }
        asm volatile("cp.async.wait_group 0;" ::: "memory");
        __syncthreads();

        float b0s = 3.4e38f, b1s = 3.4e38f, b2s = 3.4e38f, b3s = 3.4e38f;
        int   b0k = 0, b1k = 0, b2k = 0, b3k = 0;

        #pragma unroll 1
        for (int c = 0; c < 4; c++) {
            if (c < 3) chunk_async(sBbuf[(c + 1) & 1], g_B + (size_t)(c + 1) * CHUNK_BYTES, tid);

            // warp computes Mtile=wid (16 tokens) x 128 codewords
            const uint32_t aW = sA + (uint32_t)wid * NKT * 512 + aOff;
            const uint32_t sB = sBbuf[c & 1] + bOff;
            float acc[16][4];
            #pragma unroll
            for (int t8 = 0; t8 < 16; t8++)
                #pragma unroll
                for (int q = 0; q < 4; q++) acc[t8][q] = 0.f;

            #pragma unroll
            for (int kt = 0; kt < NKT; kt++) {
                uint32_t a0, a1, a2, a3;
                LDSM4(a0, a1, a2, a3, aW + (uint32_t)kt * 512);
                #pragma unroll
                for (int pr = 0; pr < 8; pr++) {
                    uint32_t r0, r1, r2, r3;   // b0/b1 of tiles 2pr, 2pr+1
                    LDSM4(r0, r1, r2, r3, sB + (uint32_t)(kt * 16 + pr * 2) * 256);
                    MMA_BF16(acc[2 * pr],     a0, a1, a2, a3, r0, r1);
                    MMA_BF16(acc[2 * pr + 1], a0, a1, a2, a3, r2, r3);
                }
            }

            // stage scores: rows = token-in-tile, cols = codeword-in-chunk
            {
                const int m0 = wid * 16 + (lane >> 2);
                #pragma unroll
                for (int t8 = 0; t8 < 16; t8++) {
                    const int n = t8 * 8 + 2 * (lane & 3);
                    *(float2*)(ssc + m0 * SSTR + n)       = make_float2(acc[t8][0], acc[t8][1]);
                    *(float2*)(ssc + (m0 + 8) * SSTR + n) = make_float2(acc[t8][2], acc[t8][3]);
                }
            }
            __syncthreads();

            // scan own token (threads 0..127): approx score = cn[k] - 2*dot
            if (tid < 128) {
                const float* rowp = ssc + tid * SSTR;
                const int kb = c * 128;
                #pragma unroll 4
                for (int n = 0; n < 128; n += 2) {
                    const float2 d2 = *(const float2*)(rowp + n);
                    TOP4(fmaf(-2.f, d2.x, scn[kb + n]),     kb + n);
                    TOP4(fmaf(-2.f, d2.y, scn[kb + n + 1]), kb + n + 1);
                }
            }
            if (c < 3) asm volatile("cp.async.wait_group 0;" ::: "memory");
            __syncthreads();
        }

        // ---- finalize token (threads 0..127) ----
        if (tid < 128) {
            const int t = t0 + tid;
            int kstar = b0k;
            const float thr = b0s + WIN;

            if (b1s <= thr) {
                const float* xp = x + (size_t)b * DT + t;
                float xn = 0.f;
                #pragma unroll
                for (int d = 0; d < Dc; d++) {
                    const float v = xp[(size_t)d * Tc];
                    xn = __fadd_rn(xn, __fmul_rn(v, v));
                }
                float be = 3.4e38f;
                if (b3s <= thr) {
                    // rare: >3 near-ties -> full exact scan (ascending k, strict <)
                    for (int k = 0; k < Kc; k++) {
                        const float* cr = cb + k * Dc;
                        float dot = 0.f;
                        #pragma unroll
                        for (int d = 0; d < Dc; d++)
                            dot = fmaf(xp[(size_t)d * Tc], __ldg(cr + d), dot);
                        const float s = __fadd_rn(fmaf(-2.f, dot, xn), scn[k]);
                        if (s < be) { be = s; kstar = k; }
                    }
                } else {
                    int nc = 2, ck[4];
                    ck[0] = b0k; ck[1] = b1k;
                    if (b2s <= thr) ck[nc++] = b2k;
                    // sort ascending k (ref tie rule = first min)
                    #pragma unroll
                    for (int i = 0; i < 2; i++)
                        #pragma unroll
                        for (int j = 0; j < 2; j++)
                            if (j + 1 < nc && ck[j + 1] < ck[j]) {
                                int tk = ck[j]; ck[j] = ck[j + 1]; ck[j + 1] = tk;
                            }
                    for (int i = 0; i < nc; i++) {
                        const int k = ck[i];
                        const float* cr = cb + k * Dc;
                        float dot = 0.f;
                        #pragma unroll
                        for (int d = 0; d < Dc; d++)
                            dot = fmaf(xp[(size_t)d * Tc], __ldg(cr + d), dot);
                        const float s = __fadd_rn(fmaf(-2.f, dot, xn), scn[k]);
                        if (s < be) { be = s; kstar = k; }
                    }
                }
            }

            // gather codeword + write both outputs (coalesced across threads)
            const float4* q = (const float4*)(cb + kstar * Dc);
            float* o0 = out + (size_t)b * DT + t;
            float* o1 = o0 + (size_t)Bc * DT;
            #pragma unroll
            for (int g = 0; g < 16; g++) {
                const float4 v = __ldg(q + g);
                const size_t r = (size_t)(4 * g) * Tc;
                o0[r] = v.x; o0[r + Tc] = v.y; o0[r + 2 * Tc] = v.z; o0[r + 3 * Tc] = v.w;
                if (write_second) {
                    o1[r] = v.x; o1[r + Tc] = v.y; o1[r + 2 * Tc] = v.z; o1[r + 3 * Tc] = v.w;
                }
            }
        }
        __syncthreads();   // protect A/scores before next tile's rebuild
    }
}

extern "C" void kernel_launch(void* const* d_in, const int* in_sizes, int n_in,
                              void* d_out, int out_size)
{
    const float* x  = (const float*)d_in[0];   // [16, 64, 8192] fp32
    const float* cb = (const float*)d_in[1];   // [512, 64] fp32
    float* out = (float*)d_out;                // 2 x [16,64,8192]

    static int inited = 0;
    if (!inited) {
        cudaFuncSetAttribute(vq_main, cudaFuncAttributeMaxDynamicSharedMemorySize,
                             SMEM_TOTAL);
        inited = 1;
    }
    const int write_second = (out_size >= 2 * Bc * DT) ? 1 : 0;

    vq_prep<<<4, 128>>>(cb);
    vq_main<<<GRID, THREADS, SMEM_TOTAL>>>(x, cb, out, write_second);
}